// round 1
// baseline (speedup 1.0000x reference)
#include <cuda_runtime.h>
#include <math.h>

// Problem constants
#define NPTS   8192
#define SS     1024
#define KK     32
#define BB     8
#define CPREV  64
#define EPSF   1e-7f

// Folded (BN-fused), transposed weights: layout [c][o]
__device__ __align__(16) float g_w1t[8 * 32];
__device__ float g_b1[32];
__device__ __align__(16) float g_w2t[32 * 64];
__device__ float g_b2[64];
__device__ __align__(16) float g_fw1t[128 * 128];
__device__ float g_fb1[128];
__device__ __align__(16) float g_fw2t[128 * 256];
__device__ float g_fb2[256];

__global__ void prep_kernel(
    const float* __restrict__ ew1, const float* __restrict__ eb1, const float* __restrict__ eg1,
    const float* __restrict__ ebeta1, const float* __restrict__ em1, const float* __restrict__ ev1,
    const float* __restrict__ ew2, const float* __restrict__ eb2, const float* __restrict__ eg2,
    const float* __restrict__ ebeta2, const float* __restrict__ em2, const float* __restrict__ ev2,
    const float* __restrict__ fw1, const float* __restrict__ fb1, const float* __restrict__ fg1,
    const float* __restrict__ fbeta1, const float* __restrict__ fm1, const float* __restrict__ fv1,
    const float* __restrict__ fw2, const float* __restrict__ fb2, const float* __restrict__ fg2,
    const float* __restrict__ fbeta2, const float* __restrict__ fm2, const float* __restrict__ fv2)
{
    int t = blockIdx.x * blockDim.x + threadIdx.x;
    int stride = gridDim.x * blockDim.x;

    // e1: [8 in][32 out]
    for (int i = t; i < 32 * 8; i += stride) {
        int o = i & 31, c = i >> 5;
        float sc = eg1[o] * rsqrtf(ev1[o] + 1e-5f);
        g_w1t[c * 32 + o] = ew1[o * 8 + c] * sc;
    }
    for (int i = t; i < 32; i += stride) {
        float sc = eg1[i] * rsqrtf(ev1[i] + 1e-5f);
        g_b1[i] = (eb1[i] - em1[i]) * sc + ebeta1[i];
    }
    // e2: [32 in][64 out]
    for (int i = t; i < 64 * 32; i += stride) {
        int o = i & 63, c = i >> 6;
        float sc = eg2[o] * rsqrtf(ev2[o] + 1e-5f);
        g_w2t[c * 64 + o] = ew2[o * 32 + c] * sc;
    }
    for (int i = t; i < 64; i += stride) {
        float sc = eg2[i] * rsqrtf(ev2[i] + 1e-5f);
        g_b2[i] = (eb2[i] - em2[i]) * sc + ebeta2[i];
    }
    // f1: [128 in][128 out]
    for (int i = t; i < 128 * 128; i += stride) {
        int o = i & 127, c = i >> 7;
        float sc = fg1[o] * rsqrtf(fv1[o] + 1e-5f);
        g_fw1t[c * 128 + o] = fw1[o * 128 + c] * sc;
    }
    for (int i = t; i < 128; i += stride) {
        float sc = fg1[i] * rsqrtf(fv1[i] + 1e-5f);
        g_fb1[i] = (fb1[i] - fm1[i]) * sc + fbeta1[i];
    }
    // f2: [128 in][256 out]
    for (int i = t; i < 256 * 128; i += stride) {
        int o = i & 255, c = i >> 8;
        float sc = fg2[o] * rsqrtf(fv2[o] + 1e-5f);
        g_fw2t[c * 256 + o] = fw2[o * 128 + c] * sc;
    }
    for (int i = t; i < 256; i += stride) {
        float sc = fg2[i] * rsqrtf(fv2[i] + 1e-5f);
        g_fb2[i] = (fb2[i] - fm2[i]) * sc + fbeta2[i];
    }
}

__device__ __forceinline__ float clamp1(float x) {
    return fminf(fmaxf(x, -1.0f + EPSF), 1.0f - EPSF);
}

#define XSTRIDE 133  // padded row stride (words) for conflict-free k-strided access

__global__ __launch_bounds__(256) void main_kernel(
    const float* __restrict__ contour,
    const float* __restrict__ loa,
    const float* __restrict__ prev,
    float* __restrict__ out)
{
    __shared__ int   gsh[KK];
    __shared__ float rif[KK][8];
    __shared__ float h1[KK][32];
    __shared__ float xin[KK][XSTRIDE];  // 64 e2 outputs + 64 gathered prev
    __shared__ float h3[KK][XSTRIDE];   // f1 outputs (128)

    const int bs   = blockIdx.x;
    const int b    = bs >> 10;       // SS = 1024
    const int s    = bs & (SS - 1);
    const int t    = threadIdx.x;
    const int lane = t & 31;
    const int warp = t >> 5;

    // numpy linspace(0, N-1, S).astype(int64)
    int nii;
    if (s == SS - 1) nii = NPTS - 1;
    else nii = (int)((double)s * ((double)(NPTS - 1) / (double)(SS - 1)));

    // ---- Phase 1: geometry features (warp 0, one thread per k) ----
    if (warp == 0) {
        const int k  = lane;
        const int g  = (nii - KK / 2 + k) & (NPTS - 1);
        const int gp = (nii - KK / 2 + k - 1) & (NPTS - 1);
        gsh[k] = g;

        const float2* cptr = (const float2*)(contour + (size_t)b * NPTS * 2);
        const float2* lptr = (const float2*)(loa + (size_t)b * NPTS * 2);
        float2 xi  = cptr[g];
        float2 lxi = lptr[g];
        float2 xp  = cptr[gp];
        float2 lxp = lptr[gp];
        float2 ci  = cptr[nii];
        float2 lci = lptr[nii];

        float vx = xi.x - ci.x, vy = xi.y - ci.y;
        float f4 = sqrtf(vx * vx + vy * vy);
        float inv = 1.0f / (f4 + EPSF);
        float ux = vx * inv, uy = vy * inv;

        float a1 = lci.x * ux + lci.y * uy;
        float a2 = -(lxi.x * ux + lxi.y * uy);
        float dp = lxi.x * lci.x + lxi.y * lci.y;
        float f3 = ((a1 < a2) ? 1.0f : -1.0f) * acosf(clamp1(dp));

        float vpx, vpy, lmx, lmy, rux, ruy;
        if (k > 0) {
            vpx = xi.x - xp.x; vpy = xi.y - xp.y;
            lmx = lxp.x;       lmy = lxp.y;
            float pvx = xp.x - ci.x, pvy = xp.y - ci.y;
            float f4p = sqrtf(pvx * pvx + pvy * pvy);
            float invp = 1.0f / (f4p + EPSF);
            rux = pvx * invp; ruy = pvy * invp;
        } else {
            vpx = vpy = lmx = lmy = rux = ruy = 0.0f;
        }
        float f8 = sqrtf(vpx * vpx + vpy * vpy);
        float inv8 = 1.0f / (f8 + EPSF);
        float upx = vpx * inv8, upy = vpy * inv8;

        float a4 = upx * lxi.x + upy * lxi.y;
        float a5 = upx * lmx + upy * lmy;
        float dp2 = lxi.x * lmx + lxi.y * lmy;
        float f7 = ((a4 < a5) ? 1.0f : -1.0f) * acosf(clamp1(dp2));
        float d2 = acosf(clamp1(ux * rux + uy * ruy));

        rif[k][0] = f4; rif[k][1] = d2; rif[k][2] = a1; rif[k][3] = a2;
        rif[k][4] = f3; rif[k][5] = a4; rif[k][6] = a5; rif[k][7] = f7;
    }
    __syncthreads();

    // ---- Phase 2: e1 (8 -> 32). o = lane, warp handles k = warp*4 .. +3 ----
    {
        const int o  = lane;
        const int k0 = warp * 4;
        float bias = g_b1[o];
        float a0 = bias, a1v = bias, a2v = bias, a3v = bias;
        #pragma unroll
        for (int c = 0; c < 8; c++) {
            float w = g_w1t[c * 32 + o];
            a0  += w * rif[k0 + 0][c];
            a1v += w * rif[k0 + 1][c];
            a2v += w * rif[k0 + 2][c];
            a3v += w * rif[k0 + 3][c];
        }
        h1[k0 + 0][o] = fmaxf(a0, 0.0f);
        h1[k0 + 1][o] = fmaxf(a1v, 0.0f);
        h1[k0 + 2][o] = fmaxf(a2v, 0.0f);
        h1[k0 + 3][o] = fmaxf(a3v, 0.0f);
    }
    __syncthreads();

    // ---- Phase 3a: e2 (32 -> 64). o = t&63, kg = t>>6 handles 8 k ----
    {
        const int o  = t & 63;
        const int k0 = (t >> 6) * 8;
        float acc[8];
        float bias = g_b2[o];
        #pragma unroll
        for (int i = 0; i < 8; i++) acc[i] = bias;
        #pragma unroll 4
        for (int c = 0; c < 32; c++) {
            float w = g_w2t[c * 64 + o];
            #pragma unroll
            for (int i = 0; i < 8; i++) acc[i] += w * h1[k0 + i][c];
        }
        #pragma unroll
        for (int i = 0; i < 8; i++) xin[k0 + i][o] = fmaxf(acc[i], 0.0f);
    }
    // ---- Phase 3b: gather prev features. k = lane, c = warp*8 .. +7 ----
    {
        const int k = lane;
        const int g = gsh[k];
        const float* pb = prev + ((size_t)b * CPREV + warp * 8) * NPTS;
        #pragma unroll
        for (int j = 0; j < 8; j++)
            xin[k][64 + warp * 8 + j] = pb[(size_t)j * NPTS + g];
    }
    __syncthreads();

    // ---- Phase 4: f1 (128 -> 128). k = lane, o-tile = warp*16 ----
    {
        const int k  = lane;
        const int ob = warp * 16;
        const float* xrow = &xin[k][0];
        float acc[16];
        #pragma unroll
        for (int j = 0; j < 16; j++) acc[j] = g_fb1[ob + j];
        #pragma unroll 4
        for (int c = 0; c < 128; c++) {
            float x = xrow[c];
            const float4* wp = (const float4*)&g_fw1t[c * 128 + ob];
            float4 w0 = wp[0], w1 = wp[1], w2 = wp[2], w3 = wp[3];
            acc[0]  += w0.x * x; acc[1]  += w0.y * x; acc[2]  += w0.z * x; acc[3]  += w0.w * x;
            acc[4]  += w1.x * x; acc[5]  += w1.y * x; acc[6]  += w1.z * x; acc[7]  += w1.w * x;
            acc[8]  += w2.x * x; acc[9]  += w2.y * x; acc[10] += w2.z * x; acc[11] += w2.w * x;
            acc[12] += w3.x * x; acc[13] += w3.y * x; acc[14] += w3.z * x; acc[15] += w3.w * x;
        }
        #pragma unroll
        for (int j = 0; j < 16; j++) h3[k][ob + j] = fmaxf(acc[j], 0.0f);
    }
    __syncthreads();

    // ---- Phase 5: f2 (128 -> 256) + max over k. k = lane, o-tile = warp*32 ----
    {
        const int k  = lane;
        const int ob = warp * 32;
        const float* xrow = &h3[k][0];
        float acc[32];
        #pragma unroll
        for (int j = 0; j < 32; j++) acc[j] = g_fb2[ob + j];
        #pragma unroll 2
        for (int c = 0; c < 128; c++) {
            float x = xrow[c];
            const float4* wp = (const float4*)&g_fw2t[c * 256 + ob];
            #pragma unroll
            for (int q = 0; q < 8; q++) {
                float4 w = wp[q];
                acc[q * 4 + 0] += w.x * x;
                acc[q * 4 + 1] += w.y * x;
                acc[q * 4 + 2] += w.z * x;
                acc[q * 4 + 3] += w.w * x;
            }
        }
        // relu + max over k (lanes) per output channel
        float res = 0.0f;
        #pragma unroll
        for (int j = 0; j < 32; j++) {
            float v = fmaxf(acc[j], 0.0f);
            v = fmaxf(v, __shfl_xor_sync(0xffffffffu, v, 16));
            v = fmaxf(v, __shfl_xor_sync(0xffffffffu, v, 8));
            v = fmaxf(v, __shfl_xor_sync(0xffffffffu, v, 4));
            v = fmaxf(v, __shfl_xor_sync(0xffffffffu, v, 2));
            v = fmaxf(v, __shfl_xor_sync(0xffffffffu, v, 1));
            if (lane == j) res = v;
        }
        // out[b][o][s], o = ob + lane
        out[((size_t)(b * 256 + ob + lane)) * SS + s] = res;
    }
}

extern "C" void kernel_launch(void* const* d_in, const int* in_sizes, int n_in,
                              void* d_out, int out_size)
{
    const float* contour = (const float*)d_in[0];
    const float* loa     = (const float*)d_in[1];
    const float* prev    = (const float*)d_in[2];

    prep_kernel<<<128, 256>>>(
        (const float*)d_in[3],  (const float*)d_in[4],  (const float*)d_in[5],
        (const float*)d_in[6],  (const float*)d_in[7],  (const float*)d_in[8],
        (const float*)d_in[9],  (const float*)d_in[10], (const float*)d_in[11],
        (const float*)d_in[12], (const float*)d_in[13], (const float*)d_in[14],
        (const float*)d_in[15], (const float*)d_in[16], (const float*)d_in[17],
        (const float*)d_in[18], (const float*)d_in[19], (const float*)d_in[20],
        (const float*)d_in[21], (const float*)d_in[22], (const float*)d_in[23],
        (const float*)d_in[24], (const float*)d_in[25], (const float*)d_in[26]);

    main_kernel<<<BB * SS, 256>>>(contour, loa, prev, (float*)d_out);
}